// round 7
// baseline (speedup 1.0000x reference)
#include <cuda_runtime.h>
#include <cuda_bf16.h>

// BlockAttnRes: per-token block attention over N=9 source rows of D=512.
//   score_n = dot(src_n, w) / sqrt(mean(src_n^2)+1e-6),  alpha = softmax(score),
//   h = sum_n alpha_n * src_n.
//
// R7 = R1 (the best variant: one CTA/token, register-resident, natural reg
// allocation, plain loads/stores) with ONE change: single-barrier softmax.
// The serial tid==0 softmax + second __syncthreads is replaced by a
// redundant per-thread softmax fused into the weighted-sum pass (exp and
// accumulation in one loop, normalize at the end). R2-R6 established that
// smem staging / prefetch / persistent grids all regress; ~80% DRAM-active
// is this stream's ceiling, so only the per-CTA critical path is left.

#define NN 9
#define DD 512
#define THREADS 128

__global__ __launch_bounds__(THREADS)
void blockattn_kernel(const float* __restrict__ src,
                      const float* __restrict__ queries,
                      const int*   __restrict__ layer_idx,
                      float*       __restrict__ out)
{
    __shared__ float s_ss[NN][4];
    __shared__ float s_dt[NN][4];

    const int tid  = threadIdx.x;
    const int lane = tid & 31;
    const int warp = tid >> 5;
    const long long token = blockIdx.x;

    const float4* base = reinterpret_cast<const float4*>(src + token * (long long)(NN * DD));

    const int li = *layer_idx;
    const float4 w4 = reinterpret_cast<const float4*>(queries + (long long)li * DD)[tid];

    // ---- Front-batched loads: all 9 rows into registers (single DRAM read) ----
    float4 v[NN];
#pragma unroll
    for (int n = 0; n < NN; n++)
        v[n] = base[n * (DD / 4) + tid];

    // ---- Per-row partials: sumsq & dot, warp-reduce, stash ----
#pragma unroll
    for (int n = 0; n < NN; n++) {
        const float4 a = v[n];
        float ssn = a.x * a.x + a.y * a.y + a.z * a.z + a.w * a.w;
        float dtn = a.x * w4.x + a.y * w4.y + a.z * w4.z + a.w * w4.w;
#pragma unroll
        for (int o = 16; o > 0; o >>= 1) {
            ssn += __shfl_xor_sync(0xffffffffu, ssn, o);
            dtn += __shfl_xor_sync(0xffffffffu, dtn, o);
        }
        if (lane == 0) {
            s_ss[n][warp] = ssn;
            s_dt[n][warp] = dtn;
        }
    }
    __syncthreads();   // the ONLY barrier

    // ---- Pass 1 over broadcast smem partials: max score ----
    float sc[NN];
    float mx = -3.4e38f;
#pragma unroll
    for (int n = 0; n < NN; n++) {
        const float S  = s_ss[n][0] + s_ss[n][1] + s_ss[n][2] + s_ss[n][3];
        const float Dt = s_dt[n][0] + s_dt[n][1] + s_dt[n][2] + s_dt[n][3];
        sc[n] = Dt * rsqrtf(S * (1.0f / DD) + 1e-6f);
        mx = fmaxf(mx, sc[n]);
    }

    // ---- Pass 2: fuse exp + weighted accumulation; normalize once ----
    float4 o = make_float4(0.f, 0.f, 0.f, 0.f);
    float sum = 0.0f;
#pragma unroll
    for (int n = 0; n < NN; n++) {
        const float e = __expf(sc[n] - mx);
        sum += e;
        o.x += e * v[n].x;
        o.y += e * v[n].y;
        o.z += e * v[n].z;
        o.w += e * v[n].w;
    }
    const float inv = 1.0f / sum;
    o.x *= inv; o.y *= inv; o.z *= inv; o.w *= inv;

    reinterpret_cast<float4*>(out + token * (long long)DD)[tid] = o;
}

extern "C" void kernel_launch(void* const* d_in, const int* in_sizes, int n_in,
                              void* d_out, int out_size)
{
    const float* src     = (const float*)d_in[0];
    const float* queries = (const float*)d_in[1];
    const int*   lidx    = (const int*)d_in[2];
    float*       out     = (float*)d_out;

    const int tokens = in_sizes[0] / (NN * DD);   // B*T = 32768
    blockattn_kernel<<<tokens, THREADS>>>(src, queries, lidx, out);
}

// round 8
// speedup vs baseline: 1.1068x; 1.1068x over previous
#include <cuda_runtime.h>
#include <cuda_bf16.h>

// BlockAttnRes: per-token block attention over N=9 source rows of D=512.
//   score_n = dot(src_n, w) / sqrt(mean(src_n^2)+1e-6),  alpha = softmax(score),
//   h = sum_n alpha_n * src_n.
//
// R8 = R1 verbatim (the empirically best variant across 7 alternatives:
// one CTA/token, register-resident rows, natural reg allocation, two
// barriers, plain loads/stores) with exactly one change: the softmax runs
// on WARP 0 with lane n owning row n (parallel rsqrt/exp, butterfly
// max/sum) instead of serially on tid==0 (~350 serial MUFU cycles).

#define NN 9
#define DD 512
#define THREADS 128

__global__ __launch_bounds__(THREADS)
void blockattn_kernel(const float* __restrict__ src,
                      const float* __restrict__ queries,
                      const int*   __restrict__ layer_idx,
                      float*       __restrict__ out)
{
    const int tid  = threadIdx.x;
    const int lane = tid & 31;
    const int warp = tid >> 5;

    const long long token = blockIdx.x;
    const float4* base = reinterpret_cast<const float4*>(src + token * (long long)(NN * DD));

    // Query row (L2-resident, broadcast across all CTAs)
    const int li = *layer_idx;
    const float4 w4 = reinterpret_cast<const float4*>(queries + (long long)li * DD)[tid];

    // ---- Phase 1: load all 9 rows into registers (front-batched, coalesced) ----
    float4 v[NN];
#pragma unroll
    for (int n = 0; n < NN; n++)
        v[n] = base[n * (DD / 4) + tid];

    // ---- Per-thread partials: sum of squares & dot with w, per row ----
    float ss[NN], dt[NN];
#pragma unroll
    for (int n = 0; n < NN; n++) {
        const float4 a = v[n];
        ss[n] = a.x * a.x + a.y * a.y + a.z * a.z + a.w * a.w;
        dt[n] = a.x * w4.x + a.y * w4.y + a.z * w4.z + a.w * w4.w;
    }

    // ---- Warp reduction ----
#pragma unroll
    for (int n = 0; n < NN; n++) {
#pragma unroll
        for (int o = 16; o > 0; o >>= 1) {
            ss[n] += __shfl_xor_sync(0xffffffffu, ss[n], o);
            dt[n] += __shfl_xor_sync(0xffffffffu, dt[n], o);
        }
    }

    // ---- Cross-warp reduction via shared ----
    __shared__ float s_ss[NN][4];
    __shared__ float s_dt[NN][4];
    __shared__ float s_alpha[NN];

    if (lane == 0) {
#pragma unroll
        for (int n = 0; n < NN; n++) {
            s_ss[n][warp] = ss[n];
            s_dt[n][warp] = dt[n];
        }
    }
    __syncthreads();

    // ---- Softmax on warp 0: lane n owns row n (parallel MUFU) ----
    if (warp == 0) {
        float sc = -3.4e38f;
        if (lane < NN) {
            const float S  = s_ss[lane][0] + s_ss[lane][1] + s_ss[lane][2] + s_ss[lane][3];
            const float Dt = s_dt[lane][0] + s_dt[lane][1] + s_dt[lane][2] + s_dt[lane][3];
            sc = Dt * rsqrtf(S * (1.0f / DD) + 1e-6f);
        }
        float mx = sc;
#pragma unroll
        for (int o = 16; o > 0; o >>= 1)
            mx = fmaxf(mx, __shfl_xor_sync(0xffffffffu, mx, o));

        float e = (lane < NN) ? __expf(sc - mx) : 0.0f;
        float sum = e;
#pragma unroll
        for (int o = 16; o > 0; o >>= 1)
            sum += __shfl_xor_sync(0xffffffffu, sum, o);

        if (lane < NN)
            s_alpha[lane] = e / sum;
    }
    __syncthreads();

    // ---- Phase 2: weighted sum from register-resident rows ----
    float4 o = make_float4(0.f, 0.f, 0.f, 0.f);
#pragma unroll
    for (int n = 0; n < NN; n++) {
        const float a = s_alpha[n];
        o.x += a * v[n].x;
        o.y += a * v[n].y;
        o.z += a * v[n].z;
        o.w += a * v[n].w;
    }

    reinterpret_cast<float4*>(out + token * (long long)DD)[tid] = o;
}

extern "C" void kernel_launch(void* const* d_in, const int* in_sizes, int n_in,
                              void* d_out, int out_size)
{
    const float* src     = (const float*)d_in[0];
    const float* queries = (const float*)d_in[1];
    const int*   lidx    = (const int*)d_in[2];
    float*       out     = (float*)d_out;

    const int tokens = in_sizes[0] / (NN * DD);   // B*T = 32768
    blockattn_kernel<<<tokens, THREADS>>>(src, queries, lidx, out);
}

// round 9
// speedup vs baseline: 1.1082x; 1.0013x over previous
#include <cuda_runtime.h>
#include <cuda_bf16.h>

// BlockAttnRes: per-token block attention over N=9 source rows of D=512.
//   score_n = dot(src_n, w) / sqrt(mean(src_n^2)+1e-6),  alpha = softmax(score),
//   h = sum_n alpha_n * src_n.
//
// R9 = R8 (winner: one CTA/token, register-resident rows, warp-0 parallel
// softmax, two barriers, 64 regs) + streaming cache hints ONLY:
//   - sources loaded with __ldcs (zero reuse -> evict-first, keep L2 sector
//     buffers free for in-flight read coalescing)
//   - output stored with __stcs (write stream doesn't displace read stream)
// Query row stays a plain cached load (reused by all 32768 CTAs).

#define NN 9
#define DD 512
#define THREADS 128

__global__ __launch_bounds__(THREADS)
void blockattn_kernel(const float* __restrict__ src,
                      const float* __restrict__ queries,
                      const int*   __restrict__ layer_idx,
                      float*       __restrict__ out)
{
    const int tid  = threadIdx.x;
    const int lane = tid & 31;
    const int warp = tid >> 5;

    const long long token = blockIdx.x;
    const float4* base = reinterpret_cast<const float4*>(src + token * (long long)(NN * DD));

    // Query row (L2-resident, broadcast across all CTAs) — cached load
    const int li = *layer_idx;
    const float4 w4 = reinterpret_cast<const float4*>(queries + (long long)li * DD)[tid];

    // ---- Phase 1: load all 9 rows into registers (streaming, coalesced) ----
    float4 v[NN];
#pragma unroll
    for (int n = 0; n < NN; n++)
        v[n] = __ldcs(base + n * (DD / 4) + tid);

    // ---- Per-thread partials: sum of squares & dot with w, per row ----
    float ss[NN], dt[NN];
#pragma unroll
    for (int n = 0; n < NN; n++) {
        const float4 a = v[n];
        ss[n] = a.x * a.x + a.y * a.y + a.z * a.z + a.w * a.w;
        dt[n] = a.x * w4.x + a.y * w4.y + a.z * w4.z + a.w * w4.w;
    }

    // ---- Warp reduction ----
#pragma unroll
    for (int n = 0; n < NN; n++) {
#pragma unroll
        for (int o = 16; o > 0; o >>= 1) {
            ss[n] += __shfl_xor_sync(0xffffffffu, ss[n], o);
            dt[n] += __shfl_xor_sync(0xffffffffu, dt[n], o);
        }
    }

    // ---- Cross-warp reduction via shared ----
    __shared__ float s_ss[NN][4];
    __shared__ float s_dt[NN][4];
    __shared__ float s_alpha[NN];

    if (lane == 0) {
#pragma unroll
        for (int n = 0; n < NN; n++) {
            s_ss[n][warp] = ss[n];
            s_dt[n][warp] = dt[n];
        }
    }
    __syncthreads();

    // ---- Softmax on warp 0: lane n owns row n (parallel MUFU) ----
    if (warp == 0) {
        float sc = -3.4e38f;
        if (lane < NN) {
            const float S  = s_ss[lane][0] + s_ss[lane][1] + s_ss[lane][2] + s_ss[lane][3];
            const float Dt = s_dt[lane][0] + s_dt[lane][1] + s_dt[lane][2] + s_dt[lane][3];
            sc = Dt * rsqrtf(S * (1.0f / DD) + 1e-6f);
        }
        float mx = sc;
#pragma unroll
        for (int o = 16; o > 0; o >>= 1)
            mx = fmaxf(mx, __shfl_xor_sync(0xffffffffu, mx, o));

        float e = (lane < NN) ? __expf(sc - mx) : 0.0f;
        float sum = e;
#pragma unroll
        for (int o = 16; o > 0; o >>= 1)
            sum += __shfl_xor_sync(0xffffffffu, sum, o);

        if (lane < NN)
            s_alpha[lane] = e / sum;
    }
    __syncthreads();

    // ---- Phase 2: weighted sum from register-resident rows ----
    float4 o = make_float4(0.f, 0.f, 0.f, 0.f);
#pragma unroll
    for (int n = 0; n < NN; n++) {
        const float a = s_alpha[n];
        o.x += a * v[n].x;
        o.y += a * v[n].y;
        o.z += a * v[n].z;
        o.w += a * v[n].w;
    }

    __stcs(reinterpret_cast<float4*>(out + token * (long long)DD) + tid, o);
}

extern "C" void kernel_launch(void* const* d_in, const int* in_sizes, int n_in,
                              void* d_out, int out_size)
{
    const float* src     = (const float*)d_in[0];
    const float* queries = (const float*)d_in[1];
    const int*   lidx    = (const int*)d_in[2];
    float*       out     = (float*)d_out;

    const int tokens = in_sizes[0] / (NN * DD);   // B*T = 32768
    blockattn_kernel<<<tokens, THREADS>>>(src, queries, lidx, out);
}